// round 6
// baseline (speedup 1.0000x reference)
#include <cuda_runtime.h>
#include <cstdint>

// FastRP link prediction, dedup two-phase:
//   1) clear flags + softmax weights
//   2) mark referenced nodes
//   3) build emb[node] only for marked nodes, in ascending node order (streaming)
//   4) gather emb per edge (L2-resident), distance + sigmoid
// Unique-node traffic floor: ~137.7k distinct nodes * 3072 B = ~423 MB
// vs 544 MB measured for the direct per-edge gather.

#define P_PATHS 4
#define K_POWERS 3
#define PK 12
#define DIM 64
#define NMAX 250000

__device__ int   g_flags[NMAX];        // 1 MB
__device__ float g_emb[(size_t)NMAX * DIM]; // 64 MB scratch
__device__ float g_w[PK];

// ---------------- kernel 1: clear flags + softmax weights ----------------
__global__ __launch_bounds__(256) void clear_kernel(const float* __restrict__ fw, int N)
{
    int i = blockIdx.x * blockDim.x + threadIdx.x;
    if (i < N) g_flags[i] = 0;
    if (i == 0) {
        #pragma unroll
        for (int p = 0; p < P_PATHS; p++) {
            float a = fw[p * K_POWERS + 0];
            float b = fw[p * K_POWERS + 1];
            float c = fw[p * K_POWERS + 2];
            float m = fmaxf(a, fmaxf(b, c));
            float ea = __expf(a - m);
            float eb = __expf(b - m);
            float ec = __expf(c - m);
            float inv = 1.0f / (ea + eb + ec);
            g_w[p * K_POWERS + 0] = ea * inv;
            g_w[p * K_POWERS + 1] = eb * inv;
            g_w[p * K_POWERS + 2] = ec * inv;
        }
    }
}

// ---------------- kernel 2: mark referenced nodes ----------------
__global__ __launch_bounds__(256) void mark_kernel(
    const int* __restrict__ idx_i, const int* __restrict__ idx_j, int E)
{
    int r = blockIdx.x * blockDim.x + threadIdx.x;
    if (r < E)          g_flags[__ldg(idx_i + r)] = 1;
    else if (r < 2 * E) g_flags[__ldg(idx_j + r - E)] = 1;
}

// ---------------- kernel 3: build emb for marked nodes (node order) -------
// 16 threads per node, each owns one float4 (4 dims). Block 256 = 16 nodes.
__global__ __launch_bounds__(256) void build_kernel(
    const float* __restrict__ feats, int N)
{
    const int node = (blockIdx.x * blockDim.x + threadIdx.x) >> 4;
    if (node >= N) return;
    if (!g_flags[node]) return;   // uniform per 16-thread group

    const int l = threadIdx.x & 15;

    float w[PK];
    #pragma unroll
    for (int pk = 0; pk < PK; pk++) w[pk] = g_w[pk];

    const float4* __restrict__ f4 = (const float4*)feats;
    const int base = node * 16 + l;        // < 4M, fits int
    const int stride16 = N * 16;           // float4 stride per slice

    float ax = 0.f, ay = 0.f, az = 0.f, aw = 0.f;
    #pragma unroll
    for (int pk = 0; pk < PK; pk++) {
        float4 v = __ldg(f4 + pk * stride16 + base);  // byte off < 768MB, ok in int
        ax = fmaf(w[pk], v.x, ax);
        ay = fmaf(w[pk], v.y, ay);
        az = fmaf(w[pk], v.z, az);
        aw = fmaf(w[pk], v.w, aw);
    }
    ((float4*)g_emb)[base] = make_float4(ax, ay, az, aw);
}

// ---------------- kernel 4: gather + score ----------------
__global__ __launch_bounds__(256) void gather_kernel(
    const float* __restrict__ intercept,
    const int* __restrict__ idx_i, const int* __restrict__ idx_j,
    float* __restrict__ out, int E)
{
    const int gwarp = (blockIdx.x * blockDim.x + threadIdx.x) >> 5;
    const int lane  = threadIdx.x & 31;
    if (gwarp >= E) return;

    const int ni = __ldg(idx_i + gwarp);
    const int nj = __ldg(idx_j + gwarp);
    const int node = (lane < 16) ? ni : nj;
    const int d4 = lane & 15;

    float4 v = ((const float4*)g_emb)[node * 16 + d4];

    const unsigned FULL = 0xffffffffu;
    float dx = v.x - __shfl_xor_sync(FULL, v.x, 16);
    float dy = v.y - __shfl_xor_sync(FULL, v.y, 16);
    float dz = v.z - __shfl_xor_sync(FULL, v.z, 16);
    float dw = v.w - __shfl_xor_sync(FULL, v.w, 16);
    float s = dx * dx + dy * dy + dz * dz + dw * dw;

    #pragma unroll
    for (int off = 8; off >= 1; off >>= 1)
        s += __shfl_xor_sync(FULL, s, off);

    if (lane == 0) {
        float logit = __ldg(intercept) - s * (1.0f / (float)DIM);
        out[gwarp] = 1.0f / (1.0f + __expf(-logit));
    }
}

// ---------------- fallback: direct per-edge gather (proven R3 kernel) -----
__global__ __launch_bounds__(256) void fastrp_edge_kernel(
    const float* __restrict__ feats, const float* __restrict__ fw,
    const float* __restrict__ intercept,
    const int* __restrict__ idx_i, const int* __restrict__ idx_j,
    float* __restrict__ out, int E, int N)
{
    const int gwarp = (blockIdx.x * blockDim.x + threadIdx.x) >> 5;
    const int lane  = threadIdx.x & 31;
    if (gwarp >= E) return;

    float w[PK];
    #pragma unroll
    for (int p = 0; p < P_PATHS; p++) {
        float a = __ldg(fw + p * K_POWERS + 0);
        float b = __ldg(fw + p * K_POWERS + 1);
        float c = __ldg(fw + p * K_POWERS + 2);
        float m = fmaxf(a, fmaxf(b, c));
        float ea = __expf(a - m), eb = __expf(b - m), ec = __expf(c - m);
        float inv = 1.0f / (ea + eb + ec);
        w[p * K_POWERS + 0] = ea * inv;
        w[p * K_POWERS + 1] = eb * inv;
        w[p * K_POWERS + 2] = ec * inv;
    }

    const int ni = __ldg(idx_i + gwarp);
    const int nj = __ldg(idx_j + gwarp);
    const long long node = (lane < 16) ? (long long)ni : (long long)nj;
    const int d4 = lane & 15;

    const float4* __restrict__ f4 = (const float4*)feats;
    const long long nodebase = node * 16 + d4;
    const long long stride16 = (long long)N * 16;

    float ax = 0.f, ay = 0.f, az = 0.f, aw = 0.f;
    #pragma unroll
    for (int pk = 0; pk < PK; pk++) {
        float4 v = __ldg(f4 + (long long)pk * stride16 + nodebase);
        ax = fmaf(w[pk], v.x, ax);
        ay = fmaf(w[pk], v.y, ay);
        az = fmaf(w[pk], v.z, az);
        aw = fmaf(w[pk], v.w, aw);
    }

    const unsigned FULL = 0xffffffffu;
    float dx = ax - __shfl_xor_sync(FULL, ax, 16);
    float dy = ay - __shfl_xor_sync(FULL, ay, 16);
    float dz = az - __shfl_xor_sync(FULL, az, 16);
    float dw = aw - __shfl_xor_sync(FULL, aw, 16);
    float s = dx * dx + dy * dy + dz * dz + dw * dw;

    #pragma unroll
    for (int off = 8; off >= 1; off >>= 1)
        s += __shfl_xor_sync(FULL, s, off);

    if (lane == 0) {
        float logit = __ldg(intercept) - s * (1.0f / (float)DIM);
        out[gwarp] = 1.0f / (1.0f + __expf(-logit));
    }
}

extern "C" void kernel_launch(void* const* d_in, const int* in_sizes, int n_in,
                              void* d_out, int out_size)
{
    const float* feats     = (const float*)d_in[0];
    const float* fw        = (const float*)d_in[1];
    const float* intercept = (const float*)d_in[2];
    const int*   idx_i     = (const int*)d_in[3];
    const int*   idx_j     = (const int*)d_in[4];
    float*       out       = (float*)d_out;

    const int E = in_sizes[3];
    const int N = in_sizes[0] / (PK * DIM);

    if (N <= NMAX) {
        clear_kernel<<<(N + 255) / 256, 256>>>(fw, N);
        mark_kernel<<<(2 * E + 255) / 256, 256>>>(idx_i, idx_j, E);
        build_kernel<<<(N * 16 + 255) / 256, 256>>>(feats, N);
        gather_kernel<<<(E * 32 + 255) / 256, 256>>>(intercept, idx_i, idx_j, out, E);
    } else {
        const int blocks = (E + 7) / 8;
        fastrp_edge_kernel<<<blocks, 256>>>(feats, fw, intercept, idx_i, idx_j, out, E, N);
    }
}

// round 7
// speedup vs baseline: 1.1443x; 1.1443x over previous
#include <cuda_runtime.h>
#include <cuda_fp16.h>
#include <cstdint>

// FastRP link prediction, dedup two-phase with fp16 emb table:
//   1) clear byte-flags + softmax weights
//   2) mark referenced nodes (byte scatter)
//   3) build emb16[node] (fp16) only for marked nodes, ascending node order
//   4) gather: thread-per-edge, 16 independent LDG.128, fp16 math -> fp32 accum
// Unique-node read floor: ~137.7k nodes * 3072 B = ~423 MB.

#define P_PATHS 4
#define K_POWERS 3
#define PK 12
#define DIM 64
#define NMAX 250000

__device__ unsigned char g_flags[NMAX];                 // 250 KB
__device__ uint4         g_emb16[(size_t)NMAX * 8];     // 32 MB (64 halves/node)
__device__ float         g_w[PK];

// ---------------- kernel 1: clear flags + softmax weights ----------------
__global__ __launch_bounds__(256) void clear_kernel(const float* __restrict__ fw, int N)
{
    int i = blockIdx.x * blockDim.x + threadIdx.x;
    int n4 = (N + 3) >> 2;
    if (i < n4) ((uint32_t*)g_flags)[i] = 0;   // NMAX divisible by 4
    if (i == 0) {
        #pragma unroll
        for (int p = 0; p < P_PATHS; p++) {
            float a = fw[p * K_POWERS + 0];
            float b = fw[p * K_POWERS + 1];
            float c = fw[p * K_POWERS + 2];
            float m = fmaxf(a, fmaxf(b, c));
            float ea = __expf(a - m);
            float eb = __expf(b - m);
            float ec = __expf(c - m);
            float inv = 1.0f / (ea + eb + ec);
            g_w[p * K_POWERS + 0] = ea * inv;
            g_w[p * K_POWERS + 1] = eb * inv;
            g_w[p * K_POWERS + 2] = ec * inv;
        }
    }
}

// ---------------- kernel 2: mark referenced nodes ----------------
__global__ __launch_bounds__(256) void mark_kernel(
    const int* __restrict__ idx_i, const int* __restrict__ idx_j, int E)
{
    int r = blockIdx.x * blockDim.x + threadIdx.x;
    if (r < E)          g_flags[__ldg(idx_i + r)] = 1;
    else if (r < 2 * E) g_flags[__ldg(idx_j + r - E)] = 1;
}

// ---------------- kernel 3: build fp16 emb for marked nodes ---------------
// 16 threads per node, each owns one float4 (4 dims) -> 4 halves (uint2).
__global__ __launch_bounds__(256) void build_kernel(
    const float* __restrict__ feats, int N)
{
    const int node = (blockIdx.x * blockDim.x + threadIdx.x) >> 4;
    if (node >= N) return;
    if (!g_flags[node]) return;   // uniform per 16-thread group

    const int l = threadIdx.x & 15;

    float w[PK];
    #pragma unroll
    for (int pk = 0; pk < PK; pk++) w[pk] = g_w[pk];

    const float4* __restrict__ f4 = (const float4*)feats;
    const int base = node * 16 + l;
    const int stride16 = N * 16;

    float ax = 0.f, ay = 0.f, az = 0.f, aw = 0.f;
    #pragma unroll
    for (int pk = 0; pk < PK; pk++) {
        float4 v = __ldg(f4 + pk * stride16 + base);
        ax = fmaf(w[pk], v.x, ax);
        ay = fmaf(w[pk], v.y, ay);
        az = fmaf(w[pk], v.z, az);
        aw = fmaf(w[pk], v.w, aw);
    }

    __half2 h0 = __floats2half2_rn(ax, ay);
    __half2 h1 = __floats2half2_rn(az, aw);
    uint2 packed;
    packed.x = *reinterpret_cast<uint32_t*>(&h0);
    packed.y = *reinterpret_cast<uint32_t*>(&h1);
    ((uint2*)g_emb16)[base] = packed;   // half-warp writes 128B contiguous
}

// ---------------- kernel 4: gather + score (thread per edge) --------------
__global__ __launch_bounds__(256) void gather_kernel(
    const float* __restrict__ intercept,
    const int* __restrict__ idx_i, const int* __restrict__ idx_j,
    float* __restrict__ out, int E)
{
    const int e = blockIdx.x * blockDim.x + threadIdx.x;
    if (e >= E) return;

    const int ni = __ldg(idx_i + e);
    const int nj = __ldg(idx_j + e);

    const uint4* __restrict__ pi = g_emb16 + (size_t)ni * 8;
    const uint4* __restrict__ pj = g_emb16 + (size_t)nj * 8;

    uint4 a[8], b[8];
    #pragma unroll
    for (int c = 0; c < 8; c++) a[c] = __ldg(pi + c);
    #pragma unroll
    for (int c = 0; c < 8; c++) b[c] = __ldg(pj + c);

    float s = 0.f;
    #pragma unroll
    for (int c = 0; c < 8; c++) {
        const uint32_t* ua = reinterpret_cast<const uint32_t*>(&a[c]);
        const uint32_t* ub = reinterpret_cast<const uint32_t*>(&b[c]);
        #pragma unroll
        for (int q = 0; q < 4; q++) {
            __half2 ha = *reinterpret_cast<const __half2*>(&ua[q]);
            __half2 hb = *reinterpret_cast<const __half2*>(&ub[q]);
            __half2 d = __hsub2(ha, hb);
            float2 f = __half22float2(d);
            s = fmaf(f.x, f.x, s);
            s = fmaf(f.y, f.y, s);
        }
    }

    float logit = __ldg(intercept) - s * (1.0f / (float)DIM);
    out[e] = 1.0f / (1.0f + __expf(-logit));
}

// ---------------- fallback: direct per-edge gather (proven R3 kernel) -----
__global__ __launch_bounds__(256) void fastrp_edge_kernel(
    const float* __restrict__ feats, const float* __restrict__ fw,
    const float* __restrict__ intercept,
    const int* __restrict__ idx_i, const int* __restrict__ idx_j,
    float* __restrict__ out, int E, int N)
{
    const int gwarp = (blockIdx.x * blockDim.x + threadIdx.x) >> 5;
    const int lane  = threadIdx.x & 31;
    if (gwarp >= E) return;

    float w[PK];
    #pragma unroll
    for (int p = 0; p < P_PATHS; p++) {
        float a = __ldg(fw + p * K_POWERS + 0);
        float b = __ldg(fw + p * K_POWERS + 1);
        float c = __ldg(fw + p * K_POWERS + 2);
        float m = fmaxf(a, fmaxf(b, c));
        float ea = __expf(a - m), eb = __expf(b - m), ec = __expf(c - m);
        float inv = 1.0f / (ea + eb + ec);
        w[p * K_POWERS + 0] = ea * inv;
        w[p * K_POWERS + 1] = eb * inv;
        w[p * K_POWERS + 2] = ec * inv;
    }

    const int ni = __ldg(idx_i + gwarp);
    const int nj = __ldg(idx_j + gwarp);
    const long long node = (lane < 16) ? (long long)ni : (long long)nj;
    const int d4 = lane & 15;

    const float4* __restrict__ f4 = (const float4*)feats;
    const long long nodebase = node * 16 + d4;
    const long long stride16 = (long long)N * 16;

    float ax = 0.f, ay = 0.f, az = 0.f, aw = 0.f;
    #pragma unroll
    for (int pk = 0; pk < PK; pk++) {
        float4 v = __ldg(f4 + (long long)pk * stride16 + nodebase);
        ax = fmaf(w[pk], v.x, ax);
        ay = fmaf(w[pk], v.y, ay);
        az = fmaf(w[pk], v.z, az);
        aw = fmaf(w[pk], v.w, aw);
    }

    const unsigned FULL = 0xffffffffu;
    float dx = ax - __shfl_xor_sync(FULL, ax, 16);
    float dy = ay - __shfl_xor_sync(FULL, ay, 16);
    float dz = az - __shfl_xor_sync(FULL, az, 16);
    float dw = aw - __shfl_xor_sync(FULL, aw, 16);
    float s = dx * dx + dy * dy + dz * dz + dw * dw;

    #pragma unroll
    for (int off = 8; off >= 1; off >>= 1)
        s += __shfl_xor_sync(FULL, s, off);

    if (lane == 0) {
        float logit = __ldg(intercept) - s * (1.0f / (float)DIM);
        out[gwarp] = 1.0f / (1.0f + __expf(-logit));
    }
}

extern "C" void kernel_launch(void* const* d_in, const int* in_sizes, int n_in,
                              void* d_out, int out_size)
{
    const float* feats     = (const float*)d_in[0];
    const float* fw        = (const float*)d_in[1];
    const float* intercept = (const float*)d_in[2];
    const int*   idx_i     = (const int*)d_in[3];
    const int*   idx_j     = (const int*)d_in[4];
    float*       out       = (float*)d_out;

    const int E = in_sizes[3];
    const int N = in_sizes[0] / (PK * DIM);

    if (N <= NMAX) {
        clear_kernel<<<(((N + 3) / 4) + 255) / 256, 256>>>(fw, N);
        mark_kernel<<<(2 * E + 255) / 256, 256>>>(idx_i, idx_j, E);
        build_kernel<<<(N * 16 + 255) / 256, 256>>>(feats, N);
        gather_kernel<<<(E + 255) / 256, 256>>>(intercept, idx_i, idx_j, out, E);
    } else {
        const int blocks = (E + 7) / 8;
        fastrp_edge_kernel<<<blocks, 256>>>(feats, fw, intercept, idx_i, idx_j, out, E, N);
    }
}